// round 16
// baseline (speedup 1.0000x reference)
#include <cuda_runtime.h>
#include <cuda_fp16.h>
#include <math.h>
#include <stdint.h>

// ---------------- problem dims ----------------
#define BB   2
#define TT   2048
#define DD   1024
#define NHH  16
#define HDD  64
#define FFF  4096
#define NLL  2
#define VV   32000
#define MR   (BB*TT)          // 4096 token rows
#define EPSF 1.1920929e-07f

// ---------------- fp32 scratch ----------------
__device__ float g_h  [(size_t)MR*DD];
__device__ float g_ffs[(size_t)MR*FFF];

// ---------------- fp16 scratch ----------------
__device__ __half g_wqkv[(size_t)NLL*3*DD*DD];
__device__ __half g_wo  [(size_t)NLL*DD*DD];
__device__ __half g_wg  [(size_t)NLL*FFF*DD];
__device__ __half g_wu  [(size_t)NLL*FFF*DD];
__device__ __half g_wdn [(size_t)NLL*DD*FFF];
__device__ __half g_whd [(size_t)VV*DD];
__device__ __half g_n_h [(size_t)MR*DD],  g_n_l [(size_t)MR*DD];
__device__ __half g_qkvh[(size_t)MR*3*DD], g_qkvl[(size_t)MR*3*DD];
__device__ __half g_at_h[(size_t)MR*DD],  g_at_l[(size_t)MR*DD];
__device__ __half g_ff_h[(size_t)MR*FFF];

// ================= helpers =================
__device__ __forceinline__ uint32_t smem_u32(const void* p) {
    uint32_t a;
    asm("{ .reg .u64 t; cvta.to.shared.u64 t, %1; cvt.u32.u64 %0, t; }" : "=r"(a) : "l"(p));
    return a;
}
__device__ __forceinline__ uint32_t packh2(float lo, float hi) {
    uint32_t r;
    asm("cvt.rn.f16x2.f32 %0, %1, %2;" : "=r"(r) : "f"(hi), "f"(lo));
    return r;
}

#define MMA16(accfg, A, B0, B1) \
    asm volatile("mma.sync.aligned.m16n8k16.row.col.f32.f16.f16.f32 " \
        "{%0,%1,%2,%3}, {%4,%5,%6,%7}, {%8,%9}, {%0,%1,%2,%3};" \
        : "+f"((accfg)[0]), "+f"((accfg)[1]), "+f"((accfg)[2]), "+f"((accfg)[3]) \
        : "r"((A)[0]), "r"((A)[1]), "r"((A)[2]), "r"((A)[3]), "r"(B0), "r"(B1))

// ================= weight convert: float -> fp16 =================
__global__ __launch_bounds__(256) void convert4_kernel(const float4* __restrict__ src,
                                                       __half* __restrict__ dst,
                                                       size_t n4) {
    size_t stride = (size_t)gridDim.x * blockDim.x;
    for (size_t i = (size_t)blockIdx.x * blockDim.x + threadIdx.x; i < n4; i += stride) {
        float4 v = src[i];
        __half hx = __float2half_rn(v.x), hy = __float2half_rn(v.y);
        __half hz = __float2half_rn(v.z), hw = __float2half_rn(v.w);
        ((ushort4*)dst)[i] = make_ushort4(__half_as_ushort(hx), __half_as_ushort(hy),
                                          __half_as_ushort(hz), __half_as_ushort(hw));
    }
}

// ================= embedding =================
__global__ __launch_bounds__(256) void embed_kernel(const int* __restrict__ x,
                                                    const float* __restrict__ emb,
                                                    float* __restrict__ h) {
    int row = blockIdx.x;
    int tok = x[row];
    ((float4*)(h + (size_t)row * DD))[threadIdx.x] =
        ((const float4*)(emb + (size_t)tok * DD))[threadIdx.x];
}

// ================= RMSNorm -> fp16 hi/lo =================
__global__ __launch_bounds__(256) void rmsnorm_split(const float* __restrict__ x,
                                                     const float* __restrict__ w,
                                                     __half* __restrict__ hi,
                                                     __half* __restrict__ lo) {
    int row = blockIdx.x, t = threadIdx.x;
    float4 v = ((const float4*)(x + (size_t)row * DD))[t];
    float ss = v.x*v.x + v.y*v.y + v.z*v.z + v.w*v.w;
    #pragma unroll
    for (int o = 16; o > 0; o >>= 1) ss += __shfl_xor_sync(0xffffffffu, ss, o);
    __shared__ float wsum[8];
    if ((t & 31) == 0) wsum[t >> 5] = ss;
    __syncthreads();
    float tot = 0.f;
    #pragma unroll
    for (int i = 0; i < 8; i++) tot += wsum[i];
    float rs = rsqrtf(tot * (1.0f / (float)DD) + EPSF);
    float4 wv = ((const float4*)w)[t];
    float o0 = v.x * rs * wv.x, o1 = v.y * rs * wv.y;
    float o2 = v.z * rs * wv.z, o3 = v.w * rs * wv.w;
    __half h0 = __float2half_rn(o0), h1 = __float2half_rn(o1);
    __half h2 = __float2half_rn(o2), h3 = __float2half_rn(o3);
    ((ushort4*)(hi + (size_t)row * DD))[t] =
        make_ushort4(__half_as_ushort(h0), __half_as_ushort(h1),
                     __half_as_ushort(h2), __half_as_ushort(h3));
    __half l0 = __float2half_rn(o0 - __half2float(h0));
    __half l1 = __float2half_rn(o1 - __half2float(h1));
    __half l2 = __float2half_rn(o2 - __half2float(h2));
    __half l3 = __float2half_rn(o3 - __half2float(h3));
    ((ushort4*)(lo + (size_t)row * DD))[t] =
        make_ushort4(__half_as_ushort(l0), __half_as_ushort(l1),
                     __half_as_ushort(l2), __half_as_ushort(l3));
}

// ================= HMMA GEMM (2m x 4n, k64 double buffer) ========================
// passes=2: full hi+lo A. passes=1: hi only (LM head, FFN down-proj).
// epi: 0 fp32; 1 fp32+aux; 2 silu fp32; 3 (acc+bias)*aux -> fp16 hi(+lo);
//      4 (acc+bias) -> fp16 hi+lo (qkv output).
#define GSTAGE 49152
#define GSMEM (2 * GSTAGE)

__global__ __launch_bounds__(256, 2) void gemm_mma(
    const __half* __restrict__ ahi, const __half* __restrict__ alo,
    const __half* __restrict__ w,
    const float* __restrict__ bias, const float* __restrict__ aux,
    float* outf, __half* ohi, __half* olo,
    int N, int K, int epi, int passes)
{
    extern __shared__ __align__(1024) char smem[];
    const int tid = threadIdx.x;
    const int wid = tid >> 5, lane = tid & 31;
    const int mt = blockIdx.x, nt = blockIdx.y;
    const int warp_m = wid >> 2, warp_n = wid & 3;   // 2m x 4n
    const uint32_t sbase = smem_u32(smem);

    float acc[4][4][4];
    #pragma unroll
    for (int f = 0; f < 4; f++)
        #pragma unroll
        for (int g = 0; g < 4; g++)
            #pragma unroll
            for (int e = 0; e < 4; e++) acc[f][g][e] = 0.f;

    const int nc = K >> 6;   // 64-wide k-chunks

    auto prefetch = [&](int kc, int b) {
        const size_t koff = (size_t)kc << 6;
        const uint32_t bufo = sbase + (uint32_t)b * (uint32_t)GSTAGE;
        const __half* bases[3] = {
            ahi + ((size_t)mt * 128) * K + koff,
            alo + ((size_t)mt * 128) * K + koff,
            w   + ((size_t)nt * 128) * K + koff };
        #pragma unroll
        for (int rep = 0; rep < 12; ++rep) {
            const int idx = tid + 256 * rep;          // 0..3071
            const int tile = idx >> 10;               // 0..2
            if (passes == 1 && tile == 1) continue;   // skip dead Alo stream
            const int t  = idx & 1023;
            const int r  = t >> 3, c8 = t & 7;
            const __half* g = bases[tile] + (size_t)r * K + c8 * 8;
            const uint32_t dst = bufo + (uint32_t)tile * 16384u
                               + (uint32_t)(r * 128 + ((c8 ^ (r & 7)) << 4));
            asm volatile("cp.async.cg.shared.global [%0], [%1], 16;" :: "r"(dst), "l"(g));
        }
        asm volatile("cp.async.commit_group;" ::: "memory");
    };

    prefetch(0, 0);
    for (int c = 0; c < nc; ++c) {
        if (c + 1 < nc) {
            prefetch(c + 1, (c + 1) & 1);
            asm volatile("cp.async.wait_group 1;" ::: "memory");
        } else {
            asm volatile("cp.async.wait_group 0;" ::: "memory");
        }
        __syncthreads();

        const uint32_t buf = sbase + (uint32_t)(c & 1) * (uint32_t)GSTAGE;
        const uint32_t a_hi_b = buf, a_lo_b = buf + 16384u, b_b = buf + 32768u;

        #pragma unroll
        for (int s = 0; s < 4; ++s) {
            const int arow = warp_m * 64 + (lane & 15);
            const int ach  = s * 2 + (lane >> 4);
            const int brow = warp_n * 32 + (lane & 7);
            const int bch  = s * 2 + ((lane >> 3) & 1);
            uint32_t aoff[4], boff[4];
            #pragma unroll
            for (int f = 0; f < 4; ++f) {
                const int row = arow + f * 16;
                aoff[f] = row * 128 + ((ach ^ (row & 7)) << 4);
            }
            #pragma unroll
            for (int g = 0; g < 4; ++g) {
                const int row = brow + g * 8;
                boff[g] = row * 128 + ((bch ^ (row & 7)) << 4);
            }

            uint32_t A[4][4], Bv[4][2];
            #pragma unroll
            for (int g = 0; g < 4; ++g)
                asm volatile("ldmatrix.sync.aligned.m8n8.x2.shared.b16 {%0,%1}, [%2];"
                    : "=r"(Bv[g][0]), "=r"(Bv[g][1]) : "r"(b_b + boff[g]));
            #pragma unroll
            for (int f = 0; f < 4; ++f)
                asm volatile("ldmatrix.sync.aligned.m8n8.x4.shared.b16 {%0,%1,%2,%3}, [%4];"
                    : "=r"(A[f][0]), "=r"(A[f][1]), "=r"(A[f][2]), "=r"(A[f][3])
                    : "r"(a_hi_b + aoff[f]));
            #pragma unroll
            for (int f = 0; f < 4; ++f)
                #pragma unroll
                for (int g = 0; g < 4; ++g)
                    MMA16(acc[f][g], A[f], Bv[g][0], Bv[g][1]);
            if (passes == 2) {
                #pragma unroll
                for (int f = 0; f < 4; ++f)
                    asm volatile("ldmatrix.sync.aligned.m8n8.x4.shared.b16 {%0,%1,%2,%3}, [%4];"
                        : "=r"(A[f][0]), "=r"(A[f][1]), "=r"(A[f][2]), "=r"(A[f][3])
                        : "r"(a_lo_b + aoff[f]));
                #pragma unroll
                for (int f = 0; f < 4; ++f)
                    #pragma unroll
                    for (int g = 0; g < 4; ++g)
                        MMA16(acc[f][g], A[f], Bv[g][0], Bv[g][1]);
            }
        }
        __syncthreads();
    }

    // ---- epilogue ----
    const int r_in = lane >> 2, c_in = (lane & 3) * 2;
    #pragma unroll
    for (int f = 0; f < 4; ++f) {
        #pragma unroll
        for (int rr = 0; rr < 2; ++rr) {
            const size_t m = (size_t)mt * 128 + warp_m * 64 + f * 16 + rr * 8 + r_in;
            float* frow = outf ? outf + m * (size_t)N : (float*)0;
            const float* arow = aux ? aux + m * (size_t)N : (const float*)0;
            #pragma unroll
            for (int g = 0; g < 4; ++g) {
                const int n = nt * 128 + warp_n * 32 + g * 8 + c_in;
                float x = acc[f][g][rr * 2 + 0];
                float y = acc[f][g][rr * 2 + 1];
                if (bias) { x += bias[n]; y += bias[n + 1]; }
                if (epi == 1) {
                    x += arow[n]; y += arow[n + 1];
                    frow[n] = x; frow[n + 1] = y;
                } else if (epi == 2) {
                    x = x / (1.f + expf(-x)); y = y / (1.f + expf(-y));
                    frow[n] = x; frow[n + 1] = y;
                } else if (epi == 3 || epi == 4) {
                    if (epi == 3) { x *= arow[n]; y *= arow[n + 1]; }
                    __half hx = __float2half_rn(x), hy = __float2half_rn(y);
                    *(ushort2*)(ohi + m * (size_t)N + n) =
                        make_ushort2(__half_as_ushort(hx), __half_as_ushort(hy));
                    if (olo) {
                        __half lx = __float2half_rn(x - __half2float(hx));
                        __half ly = __float2half_rn(y - __half2float(hy));
                        *(ushort2*)(olo + m * (size_t)N + n) =
                            make_ushort2(__half_as_ushort(lx), __half_as_ushort(ly));
                    }
                } else {
                    frow[n] = x; frow[n + 1] = y;
                }
            }
        }
    }
}

// ================= HMMA flash attention (causal), HD=64, q-tile 128 =============
// Inputs already fp16 hi/lo (from qkv GEMM epi=4): tile loads are raw 16B copies.
// Q uses hi+lo, K hi only, V hi+lo — numerics identical to prior rounds.
#define ASMEM ((128*64*2 + 3*64*64) * 2)

__global__ __launch_bounds__(256) void attn_mma(const __half* __restrict__ qh,
                                                const __half* __restrict__ ql,
                                                __half* __restrict__ ohi,
                                                __half* __restrict__ olo) {
    extern __shared__ __align__(128) __half asm_buf[];
    __half* sQh = asm_buf;                 // 128*64
    __half* sQl = sQh + 128 * 64;          // 128*64
    __half* sK  = sQl + 128 * 64;          // 64*64
    __half* sVh = sK  + 64 * 64;
    __half* sVl = sVh + 64 * 64;
    const int tid = threadIdx.x, lane = tid & 31, w = tid >> 5;
    const int qt = blockIdx.x, h = blockIdx.y, b = blockIdx.z;
    const int q0 = qt * 128;
    const uint32_t bQh = smem_u32(sQh), bQl = smem_u32(sQl), bK = smem_u32(sK);
    const uint32_t bVh = smem_u32(sVh), bVl = smem_u32(sVl);

    // load Q tile [128 x 64] hi+lo (1024 chunks, 4 per thread) — raw copies
    #pragma unroll
    for (int i = 0; i < 4; i++) {
        const int idx = tid + 256 * i;
        const int r = idx >> 3, c8 = idx & 7;
        const size_t base = ((size_t)(b * TT + q0 + r)) * (3 * DD) + h * HDD + c8 * 8;
        const uint32_t off = (uint32_t)(r * 128 + ((c8 ^ (r & 7)) << 4));
        *(uint4*)((char*)sQh + off) = *(const uint4*)(qh + base);
        *(uint4*)((char*)sQl + off) = *(const uint4*)(ql + base);
    }

    float m_a = -1e30f, m_b = -1e30f, l_a = 0.f, l_b = 0.f;
    float o[8][4];
    #pragma unroll
    for (int n = 0; n < 8; n++)
        #pragma unroll
        for (int e = 0; e < 4; e++) o[n][e] = 0.f;

    const int njt = 2 * qt + 2;
    for (int jt = 0; jt < njt; jt++) {
        const int k0 = jt * 64;
        // load K hi, V hi+lo (512 chunks, 2 per thread) — raw copies
        #pragma unroll
        for (int i = 0; i < 2; i++) {
            const int idx = tid + 256 * i;
            const int r = idx >> 3, c8 = idx & 7;
            const size_t base = ((size_t)(b * TT + k0 + r)) * (3 * DD) + h * HDD + c8 * 8;
            const uint32_t off = (uint32_t)(r * 128 + ((c8 ^ (r & 7)) << 4));
            *(uint4*)((char*)sK  + off) = *(const uint4*)(qh + base + DD);
            *(uint4*)((char*)sVh + off) = *(const uint4*)(qh + base + 2 * DD);
            *(uint4*)((char*)sVl + off) = *(const uint4*)(ql + base + 2 * DD);
        }
        __syncthreads();

        float s[8][4];
        #pragma unroll
        for (int n = 0; n < 8; n++)
            #pragma unroll
            for (int e = 0; e < 4; e++) s[n][e] = 0.f;

        #pragma unroll
        for (int t = 0; t < 4; t++) {
            const int ar = w * 16 + (lane & 15);
            const uint32_t aoff = (uint32_t)(ar * 128 + (((t * 2 + (lane >> 4)) ^ (ar & 7)) << 4));
            uint32_t Ah[4], Al[4];
            asm volatile("ldmatrix.sync.aligned.m8n8.x4.shared.b16 {%0,%1,%2,%3}, [%4];"
                : "=r"(Ah[0]), "=r"(Ah[1]), "=r"(Ah[2]), "=r"(Ah[3]) : "r"(bQh + aoff));
            asm volatile("ldmatrix.sync.aligned.m8n8.x4.shared.b16 {%0,%1,%2,%3}, [%4];"
                : "=r"(Al[0]), "=r"(Al[1]), "=r"(Al[2]), "=r"(Al[3]) : "r"(bQl + aoff));
            #pragma unroll
            for (int n = 0; n < 8; n++) {
                const int br = n * 8 + (lane & 7);
                const uint32_t boff = (uint32_t)(br * 128 +
                    (((t * 2 + ((lane >> 3) & 1)) ^ (br & 7)) << 4));
                uint32_t B0, B1;
                asm volatile("ldmatrix.sync.aligned.m8n8.x2.shared.b16 {%0,%1}, [%2];"
                    : "=r"(B0), "=r"(B1) : "r"(bK + boff));
                MMA16(s[n], Ah, B0, B1);
                MMA16(s[n], Al, B0, B1);
            }
        }

        #pragma unroll
        for (int n = 0; n < 8; n++)
            #pragma unroll
            for (int e = 0; e < 4; e++) s[n][e] *= 0.125f;
        if (jt >= 2 * qt) {
            const int rla = q0 + w * 16 + (lane >> 2), rlb = rla + 8;
            #pragma unroll
            for (int n = 0; n < 8; n++) {
                const int c0 = k0 + n * 8 + (lane & 3) * 2;
                if (c0     > rla) s[n][0] = -1e30f;
                if (c0 + 1 > rla) s[n][1] = -1e30f;
                if (c0     > rlb) s[n][2] = -1e30f;
                if (c0 + 1 > rlb) s[n][3] = -1e30f;
            }
        }

        float mx_a = -1e30f, mx_b = -1e30f;
        #pragma unroll
        for (int n = 0; n < 8; n++) {
            mx_a = fmaxf(mx_a, fmaxf(s[n][0], s[n][1]));
            mx_b = fmaxf(mx_b, fmaxf(s[n][2], s[n][3]));
        }
        mx_a = fmaxf(mx_a, __shfl_xor_sync(0xffffffffu, mx_a, 1));
        mx_a = fmaxf(mx_a, __shfl_xor_sync(0xffffffffu, mx_a, 2));
        mx_b = fmaxf(mx_b, __shfl_xor_sync(0xffffffffu, mx_b, 1));
        mx_b = fmaxf(mx_b, __shfl_xor_sync(0xffffffffu, mx_b, 2));
        const float mn_a = fmaxf(m_a, mx_a), mn_b = fmaxf(m_b, mx_b);
        const float corr_a = __expf(m_a - mn_a), corr_b = __expf(m_b - mn_b);
        m_a = mn_a; m_b = mn_b;
        float sum_a = 0.f, sum_b = 0.f;
        #pragma unroll
        for (int n = 0; n < 8; n++) {
            s[n][0] = __expf(s[n][0] - mn_a); s[n][1] = __expf(s[n][1] - mn_a);
            s[n][2] = __expf(s[n][2] - mn_b); s[n][3] = __expf(s[n][3] - mn_b);
            sum_a += s[n][0] + s[n][1];
            sum_b += s[n][2] + s[n][3];
        }
        sum_a += __shfl_xor_sync(0xffffffffu, sum_a, 1);
        sum_a += __shfl_xor_sync(0xffffffffu, sum_a, 2);
        sum_b += __shfl_xor_sync(0xffffffffu, sum_b, 1);
        sum_b += __shfl_xor_sync(0xffffffffu, sum_b, 2);
        l_a = l_a * corr_a + sum_a;
        l_b = l_b * corr_b + sum_b;
        #pragma unroll
        for (int n = 0; n < 8; n++) {
            o[n][0] *= corr_a; o[n][1] *= corr_a;
            o[n][2] *= corr_b; o[n][3] *= corr_b;
        }

        uint32_t P[4][4];
        #pragma unroll
        for (int t = 0; t < 4; t++) {
            P[t][0] = packh2(s[2*t  ][0], s[2*t  ][1]);
            P[t][1] = packh2(s[2*t  ][2], s[2*t  ][3]);
            P[t][2] = packh2(s[2*t+1][0], s[2*t+1][1]);
            P[t][3] = packh2(s[2*t+1][2], s[2*t+1][3]);
        }

        #pragma unroll
        for (int t = 0; t < 4; t++) {
            #pragma unroll
            for (int dp = 0; dp < 4; dp++) {
                const int vr = t * 16 + ((lane >> 3) & 1) * 8 + (lane & 7);
                const uint32_t voff = (uint32_t)(vr * 128 +
                    (((dp * 2 + (lane >> 4)) ^ (vr & 7)) << 4));
                uint32_t r0, r1, r2, r3;
                asm volatile("ldmatrix.sync.aligned.m8n8.x4.trans.shared.b16 {%0,%1,%2,%3}, [%4];"
                    : "=r"(r0), "=r"(r1), "=r"(r2), "=r"(r3) : "r"(bVh + voff));
                MMA16(o[2*dp], P[t], r0, r1);
                MMA16(o[2*dp+1], P[t], r2, r3);
                asm volatile("ldmatrix.sync.aligned.m8n8.x4.trans.shared.b16 {%0,%1,%2,%3}, [%4];"
                    : "=r"(r0), "=r"(r1), "=r"(r2), "=r"(r3) : "r"(bVl + voff));
                MMA16(o[2*dp], P[t], r0, r1);
                MMA16(o[2*dp+1], P[t], r2, r3);
            }
        }
        __syncthreads();
    }

    const float il_a = 1.0f / l_a, il_b = 1.0f / l_b;
    const size_t ra = (size_t)(b * TT + q0 + w * 16 + (lane >> 2));
    const size_t rb = ra + 8;
    #pragma unroll
    for (int n = 0; n < 8; n++) {
        const int col = h * HDD + n * 8 + (lane & 3) * 2;
        float v0 = o[n][0] * il_a, v1 = o[n][1] * il_a;
        __half h0 = __float2half_rn(v0), h1 = __float2half_rn(v1);
        *(ushort2*)(ohi + ra * DD + col) =
            make_ushort2(__half_as_ushort(h0), __half_as_ushort(h1));
        __half e0 = __float2half_rn(v0 - __half2float(h0));
        __half e1 = __float2half_rn(v1 - __half2float(h1));
        *(ushort2*)(olo + ra * DD + col) =
            make_ushort2(__half_as_ushort(e0), __half_as_ushort(e1));
        float v2 = o[n][2] * il_b, v3 = o[n][3] * il_b;
        __half h2 = __float2half_rn(v2), h3 = __float2half_rn(v3);
        *(ushort2*)(ohi + rb * DD + col) =
            make_ushort2(__half_as_ushort(h2), __half_as_ushort(h3));
        __half e2 = __float2half_rn(v2 - __half2float(h2));
        __half e3 = __float2half_rn(v3 - __half2float(h3));
        *(ushort2*)(olo + rb * DD + col) =
            make_ushort2(__half_as_ushort(e2), __half_as_ushort(e3));
    }
}

// ================= driver =================
extern "C" void kernel_launch(void* const* d_in, const int* in_sizes, int n_in,
                              void* d_out, int out_size) {
    const int*   x      = (const int*)  d_in[0];
    const float* emb_w  = (const float*)d_in[1];
    const float* n1_w   = (const float*)d_in[2];
    const float* n2_w   = (const float*)d_in[3];
    const float* qkv_w  = (const float*)d_in[4];
    const float* qkv_b  = (const float*)d_in[5];
    const float* o_w    = (const float*)d_in[6];
    const float* o_b    = (const float*)d_in[7];
    const float* gw     = (const float*)d_in[8];
    const float* gb     = (const float*)d_in[9];
    const float* uw     = (const float*)d_in[10];
    const float* ub     = (const float*)d_in[11];
    const float* dnw    = (const float*)d_in[12];
    const float* dnb    = (const float*)d_in[13];
    const float* norm_w = (const float*)d_in[14];
    const float* head_w = (const float*)d_in[15];
    float* out = (float*)d_out;

    float *h_, *ffs_;
    __half *wq, *wo, *wg, *wu, *wd, *wh;
    __half *nh, *nl, *qkvh, *qkvl, *ath, *atl, *ffh;
    cudaGetSymbolAddress((void**)&h_,   g_h);
    cudaGetSymbolAddress((void**)&ffs_, g_ffs);
    cudaGetSymbolAddress((void**)&wq, g_wqkv);
    cudaGetSymbolAddress((void**)&wo, g_wo);
    cudaGetSymbolAddress((void**)&wg, g_wg);
    cudaGetSymbolAddress((void**)&wu, g_wu);
    cudaGetSymbolAddress((void**)&wd, g_wdn);
    cudaGetSymbolAddress((void**)&wh, g_whd);
    cudaGetSymbolAddress((void**)&nh,   g_n_h);  cudaGetSymbolAddress((void**)&nl,   g_n_l);
    cudaGetSymbolAddress((void**)&qkvh, g_qkvh); cudaGetSymbolAddress((void**)&qkvl, g_qkvl);
    cudaGetSymbolAddress((void**)&ath,  g_at_h); cudaGetSymbolAddress((void**)&atl,  g_at_l);
    cudaGetSymbolAddress((void**)&ffh,  g_ff_h);

    cudaFuncSetAttribute(gemm_mma, cudaFuncAttributeMaxDynamicSharedMemorySize, GSMEM);
    cudaFuncSetAttribute(attn_mma, cudaFuncAttributeMaxDynamicSharedMemorySize, ASMEM);

    convert4_kernel<<<2048, 256>>>((const float4*)qkv_w, wq, (size_t)NLL*3*DD*DD/4); // 0
    embed_kernel<<<MR, 256>>>(x, emb_w, h_);                                         // 1

    for (int l = 0; l < NLL; l++) {
        const size_t oq = (size_t)l * 3 * DD * DD, oo = (size_t)l * DD * DD;
        const size_t of = (size_t)l * FFF * DD;

        rmsnorm_split<<<MR, 256>>>(h_, n1_w + (size_t)l * DD, nh, nl);               // 2

        // qkv -> fp16 hi/lo directly (epi=4)
        gemm_mma<<<dim3(MR / 128, 3 * DD / 128), 256, GSMEM>>>(                      // 3
            nh, nl, wq + oq, qkv_b + (size_t)l * 3 * DD,
            nullptr, nullptr, qkvh, qkvl, 3 * DD, DD, 4, 2);

        attn_mma<<<dim3(TT / 128, NHH, BB), 256, ASMEM>>>(qkvh, qkvl, ath, atl);     // 4

        if (l == 0) convert4_kernel<<<2048, 256>>>((const float4*)o_w, wo, (size_t)NLL*DD*DD/4);

        gemm_mma<<<dim3(MR / 128, DD / 128), 256, GSMEM>>>(
            ath, atl, wo + oo, o_b + (size_t)l * DD,
            h_, h_, nullptr, nullptr, DD, DD, 1, 2);

        rmsnorm_split<<<MR, 256>>>(h_, n2_w + (size_t)l * DD, nh, nl);

        if (l == 0) {
            convert4_kernel<<<2048, 256>>>((const float4*)gw, wg, (size_t)NLL*FFF*DD/4);
            convert4_kernel<<<2048, 256>>>((const float4*)uw, wu, (size_t)NLL*FFF*DD/4);
        }

        gemm_mma<<<dim3(MR / 128, FFF / 128), 256, GSMEM>>>(
            nh, nl, wg + of, gb + (size_t)l * FFF,
            nullptr, ffs_, nullptr, nullptr, FFF, DD, 2, 2);

        // u-GEMM: epi3 writes ff hi only (olo=null) — dn runs 1-pass
        gemm_mma<<<dim3(MR / 128, FFF / 128), 256, GSMEM>>>(
            nh, nl, wu + of, ub + (size_t)l * FFF,
            ffs_, nullptr, ffh, nullptr, FFF, DD, 3, 2);

        if (l == 0) convert4_kernel<<<2048, 256>>>((const float4*)dnw, wd, (size_t)NLL*DD*FFF/4);

        // FFN down-proj: single-pass A
        gemm_mma<<<dim3(MR / 128, DD / 128), 256, GSMEM>>>(
            ffh, nullptr, wd + of, dnb + (size_t)l * DD,
            h_, h_, nullptr, nullptr, DD, FFF, 1, 1);

        if (l == 0) convert4_kernel<<<2048, 256>>>((const float4*)head_w, wh, (size_t)VV*DD/4);
    }

    rmsnorm_split<<<MR, 256>>>(h_, norm_w, nh, nl);

    // LM head: single-pass A
    gemm_mma<<<dim3(MR / 128, VV / 128), 256, GSMEM>>>(
        nh, nl, wh, nullptr,
        nullptr, out, nullptr, nullptr, VV, DD, 0, 1);
}

// round 17
// speedup vs baseline: 1.5019x; 1.5019x over previous
#include <cuda_runtime.h>
#include <cuda_fp16.h>
#include <math.h>
#include <stdint.h>

// ---------------- problem dims ----------------
#define BB   2
#define TT   2048
#define DD   1024
#define NHH  16
#define HDD  64
#define FFF  4096
#define NLL  2
#define VV   32000
#define MR   (BB*TT)          // 4096 token rows
#define EPSF 1.1920929e-07f

// ---------------- fp32 scratch ----------------
__device__ float g_h  [(size_t)MR*DD];
__device__ float g_qkv[(size_t)MR*3*DD];
__device__ float g_ffs[(size_t)MR*FFF];

// ---------------- fp16 scratch ----------------
__device__ __half g_wqkv[(size_t)NLL*3*DD*DD];
__device__ __half g_wo  [(size_t)NLL*DD*DD];
__device__ __half g_wg  [(size_t)NLL*FFF*DD];
__device__ __half g_wu  [(size_t)NLL*FFF*DD];
__device__ __half g_wdn [(size_t)NLL*DD*FFF];
__device__ __half g_whd [(size_t)VV*DD];
__device__ __half g_n_h [(size_t)MR*DD],  g_n_l [(size_t)MR*DD];
__device__ __half g_at_h[(size_t)MR*DD];
__device__ __half g_ff_h[(size_t)MR*FFF];

// ================= helpers =================
__device__ __forceinline__ uint32_t smem_u32(const void* p) {
    uint32_t a;
    asm("{ .reg .u64 t; cvta.to.shared.u64 t, %1; cvt.u32.u64 %0, t; }" : "=r"(a) : "l"(p));
    return a;
}
__device__ __forceinline__ uint32_t packh2(float lo, float hi) {
    uint32_t r;
    asm("cvt.rn.f16x2.f32 %0, %1, %2;" : "=r"(r) : "f"(hi), "f"(lo));
    return r;
}

#define MMA16(accfg, A, B0, B1) \
    asm volatile("mma.sync.aligned.m16n8k16.row.col.f32.f16.f16.f32 " \
        "{%0,%1,%2,%3}, {%4,%5,%6,%7}, {%8,%9}, {%0,%1,%2,%3};" \
        : "+f"((accfg)[0]), "+f"((accfg)[1]), "+f"((accfg)[2]), "+f"((accfg)[3]) \
        : "r"((A)[0]), "r"((A)[1]), "r"((A)[2]), "r"((A)[3]), "r"(B0), "r"(B1))

// ================= weight convert: float -> fp16 =================
__global__ __launch_bounds__(256) void convert4_kernel(const float4* __restrict__ src,
                                                       __half* __restrict__ dst,
                                                       size_t n4) {
    size_t stride = (size_t)gridDim.x * blockDim.x;
    for (size_t i = (size_t)blockIdx.x * blockDim.x + threadIdx.x; i < n4; i += stride) {
        float4 v = src[i];
        __half hx = __float2half_rn(v.x), hy = __float2half_rn(v.y);
        __half hz = __float2half_rn(v.z), hw = __float2half_rn(v.w);
        ((ushort4*)dst)[i] = make_ushort4(__half_as_ushort(hx), __half_as_ushort(hy),
                                          __half_as_ushort(hz), __half_as_ushort(hw));
    }
}

// ================= embedding =================
__global__ __launch_bounds__(256) void embed_kernel(const int* __restrict__ x,
                                                    const float* __restrict__ emb,
                                                    float* __restrict__ h) {
    int row = blockIdx.x;
    int tok = x[row];
    ((float4*)(h + (size_t)row * DD))[threadIdx.x] =
        ((const float4*)(emb + (size_t)tok * DD))[threadIdx.x];
}

// ================= RMSNorm -> fp16 hi/lo =================
__global__ __launch_bounds__(256) void rmsnorm_split(const float* __restrict__ x,
                                                     const float* __restrict__ w,
                                                     __half* __restrict__ hi,
                                                     __half* __restrict__ lo) {
    int row = blockIdx.x, t = threadIdx.x;
    float4 v = ((const float4*)(x + (size_t)row * DD))[t];
    float ss = v.x*v.x + v.y*v.y + v.z*v.z + v.w*v.w;
    #pragma unroll
    for (int o = 16; o > 0; o >>= 1) ss += __shfl_xor_sync(0xffffffffu, ss, o);
    __shared__ float wsum[8];
    if ((t & 31) == 0) wsum[t >> 5] = ss;
    __syncthreads();
    float tot = 0.f;
    #pragma unroll
    for (int i = 0; i < 8; i++) tot += wsum[i];
    float rs = rsqrtf(tot * (1.0f / (float)DD) + EPSF);
    float4 wv = ((const float4*)w)[t];
    float o0 = v.x * rs * wv.x, o1 = v.y * rs * wv.y;
    float o2 = v.z * rs * wv.z, o3 = v.w * rs * wv.w;
    __half h0 = __float2half_rn(o0), h1 = __float2half_rn(o1);
    __half h2 = __float2half_rn(o2), h3 = __float2half_rn(o3);
    ((ushort4*)(hi + (size_t)row * DD))[t] =
        make_ushort4(__half_as_ushort(h0), __half_as_ushort(h1),
                     __half_as_ushort(h2), __half_as_ushort(h3));
    __half l0 = __float2half_rn(o0 - __half2float(h0));
    __half l1 = __float2half_rn(o1 - __half2float(h1));
    __half l2 = __float2half_rn(o2 - __half2float(h2));
    __half l3 = __float2half_rn(o3 - __half2float(h3));
    ((ushort4*)(lo + (size_t)row * DD))[t] =
        make_ushort4(__half_as_ushort(l0), __half_as_ushort(l1),
                     __half_as_ushort(l2), __half_as_ushort(l3));
}

// ================= HMMA GEMM (2m x 4n, k64 double buffer) ========================
// passes=2: full hi+lo A. passes=1: hi only (LM head, FFN down-proj, o-proj).
// epi: 0 fp32; 1 fp32+aux; 2 silu fp32; 3 (acc+bias)*aux -> fp16 hi(+lo if olo).
#define GSTAGE 49152
#define GSMEM (2 * GSTAGE)

__global__ __launch_bounds__(256, 2) void gemm_mma(
    const __half* __restrict__ ahi, const __half* __restrict__ alo,
    const __half* __restrict__ w,
    const float* __restrict__ bias, const float* __restrict__ aux,
    float* outf, __half* ohi, __half* olo,
    int N, int K, int epi, int passes)
{
    extern __shared__ __align__(1024) char smem[];
    const int tid = threadIdx.x;
    const int wid = tid >> 5, lane = tid & 31;
    const int mt = blockIdx.x, nt = blockIdx.y;
    const int warp_m = wid >> 2, warp_n = wid & 3;   // 2m x 4n
    const uint32_t sbase = smem_u32(smem);

    float acc[4][4][4];
    #pragma unroll
    for (int f = 0; f < 4; f++)
        #pragma unroll
        for (int g = 0; g < 4; g++)
            #pragma unroll
            for (int e = 0; e < 4; e++) acc[f][g][e] = 0.f;

    const int nc = K >> 6;   // 64-wide k-chunks

    // stage layout: Ahi @0, Alo @16K, W @32K ; 128 rows x 128 bytes each
    auto prefetch = [&](int kc, int b) {
        const size_t koff = (size_t)kc << 6;
        const uint32_t bufo = sbase + (uint32_t)b * (uint32_t)GSTAGE;
        const __half* bases[3] = {
            ahi + ((size_t)mt * 128) * K + koff,
            alo + ((size_t)mt * 128) * K + koff,
            w   + ((size_t)nt * 128) * K + koff };
        #pragma unroll
        for (int rep = 0; rep < 12; ++rep) {
            const int idx = tid + 256 * rep;          // 0..3071
            const int tile = idx >> 10;               // 0..2
            if (passes == 1 && tile == 1) continue;   // skip dead Alo stream
            const int t  = idx & 1023;
            const int r  = t >> 3, c8 = t & 7;
            const __half* g = bases[tile] + (size_t)r * K + c8 * 8;
            const uint32_t dst = bufo + (uint32_t)tile * 16384u
                               + (uint32_t)(r * 128 + ((c8 ^ (r & 7)) << 4));
            asm volatile("cp.async.cg.shared.global [%0], [%1], 16;" :: "r"(dst), "l"(g));
        }
        asm volatile("cp.async.commit_group;" ::: "memory");
    };

    prefetch(0, 0);
    for (int c = 0; c < nc; ++c) {
        if (c + 1 < nc) {
            prefetch(c + 1, (c + 1) & 1);
            asm volatile("cp.async.wait_group 1;" ::: "memory");
        } else {
            asm volatile("cp.async.wait_group 0;" ::: "memory");
        }
        __syncthreads();

        const uint32_t buf = sbase + (uint32_t)(c & 1) * (uint32_t)GSTAGE;
        const uint32_t a_hi_b = buf, a_lo_b = buf + 16384u, b_b = buf + 32768u;

        #pragma unroll
        for (int s = 0; s < 4; ++s) {
            const int arow = warp_m * 64 + (lane & 15);
            const int ach  = s * 2 + (lane >> 4);
            const int brow = warp_n * 32 + (lane & 7);
            const int bch  = s * 2 + ((lane >> 3) & 1);
            uint32_t aoff[4], boff[4];
            #pragma unroll
            for (int f = 0; f < 4; ++f) {
                const int row = arow + f * 16;
                aoff[f] = row * 128 + ((ach ^ (row & 7)) << 4);
            }
            #pragma unroll
            for (int g = 0; g < 4; ++g) {
                const int row = brow + g * 8;
                boff[g] = row * 128 + ((bch ^ (row & 7)) << 4);
            }

            uint32_t A[4][4], Bv[4][2];
            #pragma unroll
            for (int g = 0; g < 4; ++g)
                asm volatile("ldmatrix.sync.aligned.m8n8.x2.shared.b16 {%0,%1}, [%2];"
                    : "=r"(Bv[g][0]), "=r"(Bv[g][1]) : "r"(b_b + boff[g]));
            #pragma unroll
            for (int f = 0; f < 4; ++f)
                asm volatile("ldmatrix.sync.aligned.m8n8.x4.shared.b16 {%0,%1,%2,%3}, [%4];"
                    : "=r"(A[f][0]), "=r"(A[f][1]), "=r"(A[f][2]), "=r"(A[f][3])
                    : "r"(a_hi_b + aoff[f]));
            #pragma unroll
            for (int f = 0; f < 4; ++f)
                #pragma unroll
                for (int g = 0; g < 4; ++g)
                    MMA16(acc[f][g], A[f], Bv[g][0], Bv[g][1]);
            if (passes == 2) {
                #pragma unroll
                for (int f = 0; f < 4; ++f)
                    asm volatile("ldmatrix.sync.aligned.m8n8.x4.shared.b16 {%0,%1,%2,%3}, [%4];"
                        : "=r"(A[f][0]), "=r"(A[f][1]), "=r"(A[f][2]), "=r"(A[f][3])
                        : "r"(a_lo_b + aoff[f]));
                #pragma unroll
                for (int f = 0; f < 4; ++f)
                    #pragma unroll
                    for (int g = 0; g < 4; ++g)
                        MMA16(acc[f][g], A[f], Bv[g][0], Bv[g][1]);
            }
        }
        __syncthreads();
    }

    // ---- epilogue ----
    const int r_in = lane >> 2, c_in = (lane & 3) * 2;
    #pragma unroll
    for (int f = 0; f < 4; ++f) {
        #pragma unroll
        for (int rr = 0; rr < 2; ++rr) {
            const size_t m = (size_t)mt * 128 + warp_m * 64 + f * 16 + rr * 8 + r_in;
            float* frow = outf ? outf + m * (size_t)N : (float*)0;
            const float* arow = aux ? aux + m * (size_t)N : (const float*)0;
            #pragma unroll
            for (int g = 0; g < 4; ++g) {
                const int n = nt * 128 + warp_n * 32 + g * 8 + c_in;
                float x = acc[f][g][rr * 2 + 0];
                float y = acc[f][g][rr * 2 + 1];
                if (bias) { x += bias[n]; y += bias[n + 1]; }
                if (epi == 1) {
                    x += arow[n]; y += arow[n + 1];
                    frow[n] = x; frow[n + 1] = y;
                } else if (epi == 2) {
                    x = x / (1.f + expf(-x)); y = y / (1.f + expf(-y));
                    frow[n] = x; frow[n + 1] = y;
                } else if (epi == 3) {
                    x *= arow[n]; y *= arow[n + 1];
                    __half hx = __float2half_rn(x), hy = __float2half_rn(y);
                    *(ushort2*)(ohi + m * (size_t)N + n) =
                        make_ushort2(__half_as_ushort(hx), __half_as_ushort(hy));
                    if (olo) {
                        __half lx = __float2half_rn(x - __half2float(hx));
                        __half ly = __float2half_rn(y - __half2float(hy));
                        *(ushort2*)(olo + m * (size_t)N + n) =
                            make_ushort2(__half_as_ushort(lx), __half_as_ushort(ly));
                    }
                } else {
                    frow[n] = x; frow[n + 1] = y;
                }
            }
        }
    }
}

// ================= HMMA flash attention (causal), HD=64, q-tile 128 =============
// Output: fp16 hi only (o-proj runs single-pass).
#define ASMEM ((128*64*2 + 3*64*64) * 2)

__global__ __launch_bounds__(256) void attn_mma(const float* __restrict__ qkv,
                                                __half* __restrict__ ohi) {
    extern __shared__ __align__(128) __half asm_buf[];
    __half* sQh = asm_buf;                 // 128*64
    __half* sQl = sQh + 128 * 64;          // 128*64
    __half* sK  = sQl + 128 * 64;          // 64*64
    __half* sVh = sK  + 64 * 64;
    __half* sVl = sVh + 64 * 64;
    const int tid = threadIdx.x, lane = tid & 31, w = tid >> 5;
    const int qt = blockIdx.x, h = blockIdx.y, b = blockIdx.z;
    const int q0 = qt * 128;
    const uint32_t bQh = smem_u32(sQh), bQl = smem_u32(sQl), bK = smem_u32(sK);
    const uint32_t bVh = smem_u32(sVh), bVl = smem_u32(sVl);

    // load Q tile [128 x 64] -> hi/lo fp16, swizzled (1024 chunks, 4 per thread)
    #pragma unroll
    for (int i = 0; i < 4; i++) {
        const int idx = tid + 256 * i;
        const int r = idx >> 3, c8 = idx & 7;
        const float* src = qkv + ((size_t)(b * TT + q0 + r)) * (3 * DD) + h * HDD + c8 * 8;
        const uint32_t off = (uint32_t)(r * 128 + ((c8 ^ (r & 7)) << 4));
        __half hh[8], ll[8];
        #pragma unroll
        for (int e = 0; e < 8; e++) {
            float v = src[e];
            hh[e] = __float2half_rn(v);
            ll[e] = __float2half_rn(v - __half2float(hh[e]));
        }
        *(uint4*)((char*)sQh + off) = *(uint4*)hh;
        *(uint4*)((char*)sQl + off) = *(uint4*)ll;
    }

    float m_a = -1e30f, m_b = -1e30f, l_a = 0.f, l_b = 0.f;
    float o[8][4];
    #pragma unroll
    for (int n = 0; n < 8; n++)
        #pragma unroll
        for (int e = 0; e < 4; e++) o[n][e] = 0.f;

    const int njt = 2 * qt + 2;
    for (int jt = 0; jt < njt; jt++) {
        const int k0 = jt * 64;
        #pragma unroll
        for (int i = 0; i < 2; i++) {
            const int idx = tid + 256 * i;
            const int r = idx >> 3, c8 = idx & 7;
            const size_t base = ((size_t)(b * TT + k0 + r)) * (3 * DD) + h * HDD + c8 * 8;
            const uint32_t off = (uint32_t)(r * 128 + ((c8 ^ (r & 7)) << 4));
            __half kk[8], vh[8], vl[8];
            #pragma unroll
            for (int e = 0; e < 8; e++) {
                kk[e] = __float2half_rn(qkv[base + DD + e]);
                float v = qkv[base + 2 * DD + e];
                vh[e] = __float2half_rn(v);
                vl[e] = __float2half_rn(v - __half2float(vh[e]));
            }
            *(uint4*)((char*)sK  + off) = *(uint4*)kk;
            *(uint4*)((char*)sVh + off) = *(uint4*)vh;
            *(uint4*)((char*)sVl + off) = *(uint4*)vl;
        }
        __syncthreads();

        float s[8][4];
        #pragma unroll
        for (int n = 0; n < 8; n++)
            #pragma unroll
            for (int e = 0; e < 4; e++) s[n][e] = 0.f;

        #pragma unroll
        for (int t = 0; t < 4; t++) {
            const int ar = w * 16 + (lane & 15);
            const uint32_t aoff = (uint32_t)(ar * 128 + (((t * 2 + (lane >> 4)) ^ (ar & 7)) << 4));
            uint32_t Ah[4], Al[4];
            asm volatile("ldmatrix.sync.aligned.m8n8.x4.shared.b16 {%0,%1,%2,%3}, [%4];"
                : "=r"(Ah[0]), "=r"(Ah[1]), "=r"(Ah[2]), "=r"(Ah[3]) : "r"(bQh + aoff));
            asm volatile("ldmatrix.sync.aligned.m8n8.x4.shared.b16 {%0,%1,%2,%3}, [%4];"
                : "=r"(Al[0]), "=r"(Al[1]), "=r"(Al[2]), "=r"(Al[3]) : "r"(bQl + aoff));
            #pragma unroll
            for (int n = 0; n < 8; n++) {
                const int br = n * 8 + (lane & 7);
                const uint32_t boff = (uint32_t)(br * 128 +
                    (((t * 2 + ((lane >> 3) & 1)) ^ (br & 7)) << 4));
                uint32_t B0, B1;
                asm volatile("ldmatrix.sync.aligned.m8n8.x2.shared.b16 {%0,%1}, [%2];"
                    : "=r"(B0), "=r"(B1) : "r"(bK + boff));
                MMA16(s[n], Ah, B0, B1);
                MMA16(s[n], Al, B0, B1);
            }
        }

        #pragma unroll
        for (int n = 0; n < 8; n++)
            #pragma unroll
            for (int e = 0; e < 4; e++) s[n][e] *= 0.125f;
        if (jt >= 2 * qt) {
            const int rla = q0 + w * 16 + (lane >> 2), rlb = rla + 8;
            #pragma unroll
            for (int n = 0; n < 8; n++) {
                const int c0 = k0 + n * 8 + (lane & 3) * 2;
                if (c0     > rla) s[n][0] = -1e30f;
                if (c0 + 1 > rla) s[n][1] = -1e30f;
                if (c0     > rlb) s[n][2] = -1e30f;
                if (c0 + 1 > rlb) s[n][3] = -1e30f;
            }
        }

        float mx_a = -1e30f, mx_b = -1e30f;
        #pragma unroll
        for (int n = 0; n < 8; n++) {
            mx_a = fmaxf(mx_a, fmaxf(s[n][0], s[n][1]));
            mx_b = fmaxf(mx_b, fmaxf(s[n][2], s[n][3]));
        }
        mx_a = fmaxf(mx_a, __shfl_xor_sync(0xffffffffu, mx_a, 1));
        mx_a = fmaxf(mx_a, __shfl_xor_sync(0xffffffffu, mx_a, 2));
        mx_b = fmaxf(mx_b, __shfl_xor_sync(0xffffffffu, mx_b, 1));
        mx_b = fmaxf(mx_b, __shfl_xor_sync(0xffffffffu, mx_b, 2));
        const float mn_a = fmaxf(m_a, mx_a), mn_b = fmaxf(m_b, mx_b);
        const float corr_a = __expf(m_a - mn_a), corr_b = __expf(m_b - mn_b);
        m_a = mn_a; m_b = mn_b;
        float sum_a = 0.f, sum_b = 0.f;
        #pragma unroll
        for (int n = 0; n < 8; n++) {
            s[n][0] = __expf(s[n][0] - mn_a); s[n][1] = __expf(s[n][1] - mn_a);
            s[n][2] = __expf(s[n][2] - mn_b); s[n][3] = __expf(s[n][3] - mn_b);
            sum_a += s[n][0] + s[n][1];
            sum_b += s[n][2] + s[n][3];
        }
        sum_a += __shfl_xor_sync(0xffffffffu, sum_a, 1);
        sum_a += __shfl_xor_sync(0xffffffffu, sum_a, 2);
        sum_b += __shfl_xor_sync(0xffffffffu, sum_b, 1);
        sum_b += __shfl_xor_sync(0xffffffffu, sum_b, 2);
        l_a = l_a * corr_a + sum_a;
        l_b = l_b * corr_b + sum_b;
        #pragma unroll
        for (int n = 0; n < 8; n++) {
            o[n][0] *= corr_a; o[n][1] *= corr_a;
            o[n][2] *= corr_b; o[n][3] *= corr_b;
        }

        uint32_t P[4][4];
        #pragma unroll
        for (int t = 0; t < 4; t++) {
            P[t][0] = packh2(s[2*t  ][0], s[2*t  ][1]);
            P[t][1] = packh2(s[2*t  ][2], s[2*t  ][3]);
            P[t][2] = packh2(s[2*t+1][0], s[2*t+1][1]);
            P[t][3] = packh2(s[2*t+1][2], s[2*t+1][3]);
        }

        #pragma unroll
        for (int t = 0; t < 4; t++) {
            #pragma unroll
            for (int dp = 0; dp < 4; dp++) {
                const int vr = t * 16 + ((lane >> 3) & 1) * 8 + (lane & 7);
                const uint32_t voff = (uint32_t)(vr * 128 +
                    (((dp * 2 + (lane >> 4)) ^ (vr & 7)) << 4));
                uint32_t r0, r1, r2, r3;
                asm volatile("ldmatrix.sync.aligned.m8n8.x4.trans.shared.b16 {%0,%1,%2,%3}, [%4];"
                    : "=r"(r0), "=r"(r1), "=r"(r2), "=r"(r3) : "r"(bVh + voff));
                MMA16(o[2*dp], P[t], r0, r1);
                MMA16(o[2*dp+1], P[t], r2, r3);
                asm volatile("ldmatrix.sync.aligned.m8n8.x4.trans.shared.b16 {%0,%1,%2,%3}, [%4];"
                    : "=r"(r0), "=r"(r1), "=r"(r2), "=r"(r3) : "r"(bVl + voff));
                MMA16(o[2*dp], P[t], r0, r1);
                MMA16(o[2*dp+1], P[t], r2, r3);
            }
        }
        __syncthreads();
    }

    const float il_a = 1.0f / l_a, il_b = 1.0f / l_b;
    const size_t ra = (size_t)(b * TT + q0 + w * 16 + (lane >> 2));
    const size_t rb = ra + 8;
    #pragma unroll
    for (int n = 0; n < 8; n++) {
        const int col = h * HDD + n * 8 + (lane & 3) * 2;
        float v0 = o[n][0] * il_a, v1 = o[n][1] * il_a;
        __half h0 = __float2half_rn(v0), h1 = __float2half_rn(v1);
        *(ushort2*)(ohi + ra * DD + col) =
            make_ushort2(__half_as_ushort(h0), __half_as_ushort(h1));
        float v2 = o[n][2] * il_b, v3 = o[n][3] * il_b;
        __half h2 = __float2half_rn(v2), h3 = __float2half_rn(v3);
        *(ushort2*)(ohi + rb * DD + col) =
            make_ushort2(__half_as_ushort(h2), __half_as_ushort(h3));
    }
}

// ================= driver =================
extern "C" void kernel_launch(void* const* d_in, const int* in_sizes, int n_in,
                              void* d_out, int out_size) {
    const int*   x      = (const int*)  d_in[0];
    const float* emb_w  = (const float*)d_in[1];
    const float* n1_w   = (const float*)d_in[2];
    const float* n2_w   = (const float*)d_in[3];
    const float* qkv_w  = (const float*)d_in[4];
    const float* qkv_b  = (const float*)d_in[5];
    const float* o_w    = (const float*)d_in[6];
    const float* o_b    = (const float*)d_in[7];
    const float* gw     = (const float*)d_in[8];
    const float* gb     = (const float*)d_in[9];
    const float* uw     = (const float*)d_in[10];
    const float* ub     = (const float*)d_in[11];
    const float* dnw    = (const float*)d_in[12];
    const float* dnb    = (const float*)d_in[13];
    const float* norm_w = (const float*)d_in[14];
    const float* head_w = (const float*)d_in[15];
    float* out = (float*)d_out;

    float *h_, *qkv_, *ffs_;
    __half *wq, *wo, *wg, *wu, *wd, *wh;
    __half *nh, *nl, *ath, *ffh;
    cudaGetSymbolAddress((void**)&h_,   g_h);
    cudaGetSymbolAddress((void**)&qkv_, g_qkv);
    cudaGetSymbolAddress((void**)&ffs_, g_ffs);
    cudaGetSymbolAddress((void**)&wq, g_wqkv);
    cudaGetSymbolAddress((void**)&wo, g_wo);
    cudaGetSymbolAddress((void**)&wg, g_wg);
    cudaGetSymbolAddress((void**)&wu, g_wu);
    cudaGetSymbolAddress((void**)&wd, g_wdn);
    cudaGetSymbolAddress((void**)&wh, g_whd);
    cudaGetSymbolAddress((void**)&nh,  g_n_h);  cudaGetSymbolAddress((void**)&nl,  g_n_l);
    cudaGetSymbolAddress((void**)&ath, g_at_h);
    cudaGetSymbolAddress((void**)&ffh, g_ff_h);

    cudaFuncSetAttribute(gemm_mma, cudaFuncAttributeMaxDynamicSharedMemorySize, GSMEM);
    cudaFuncSetAttribute(attn_mma, cudaFuncAttributeMaxDynamicSharedMemorySize, ASMEM);

    convert4_kernel<<<2048, 256>>>((const float4*)qkv_w, wq, (size_t)NLL*3*DD*DD/4); // 0
    embed_kernel<<<MR, 256>>>(x, emb_w, h_);                                         // 1

    for (int l = 0; l < NLL; l++) {
        const size_t oq = (size_t)l * 3 * DD * DD, oo = (size_t)l * DD * DD;
        const size_t of = (size_t)l * FFF * DD;

        rmsnorm_split<<<MR, 256>>>(h_, n1_w + (size_t)l * DD, nh, nl);               // 2

        gemm_mma<<<dim3(MR / 128, 3 * DD / 128), 256, GSMEM>>>(                      // 3
            nh, nl, wq + oq, qkv_b + (size_t)l * 3 * DD,
            nullptr, qkv_, nullptr, nullptr, 3 * DD, DD, 0, 2);

        attn_mma<<<dim3(TT / 128, NHH, BB), 256, ASMEM>>>(qkv_, ath);                // 4

        if (l == 0) convert4_kernel<<<2048, 256>>>((const float4*)o_w, wo, (size_t)NLL*DD*DD/4);

        // o-proj: single-pass A (attention-output rounding term per layer)
        gemm_mma<<<dim3(MR / 128, DD / 128), 256, GSMEM>>>(
            ath, nullptr, wo + oo, o_b + (size_t)l * DD,
            h_, h_, nullptr, nullptr, DD, DD, 1, 1);

        rmsnorm_split<<<MR, 256>>>(h_, n2_w + (size_t)l * DD, nh, nl);

        if (l == 0) {
            convert4_kernel<<<2048, 256>>>((const float4*)gw, wg, (size_t)NLL*FFF*DD/4);
            convert4_kernel<<<2048, 256>>>((const float4*)uw, wu, (size_t)NLL*FFF*DD/4);
        }

        gemm_mma<<<dim3(MR / 128, FFF / 128), 256, GSMEM>>>(
            nh, nl, wg + of, gb + (size_t)l * FFF,
            nullptr, ffs_, nullptr, nullptr, FFF, DD, 2, 2);

        // u-GEMM: epi3 writes ff hi only (olo=null) — dn runs 1-pass
        gemm_mma<<<dim3(MR / 128, FFF / 128), 256, GSMEM>>>(
            nh, nl, wu + of, ub + (size_t)l * FFF,
            ffs_, nullptr, ffh, nullptr, FFF, DD, 3, 2);

        if (l == 0) convert4_kernel<<<2048, 256>>>((const float4*)dnw, wd, (size_t)NLL*DD*FFF/4);

        // FFN down-proj: single-pass A
        gemm_mma<<<dim3(MR / 128, DD / 128), 256, GSMEM>>>(
            ffh, nullptr, wd + of, dnb + (size_t)l * DD,
            h_, h_, nullptr, nullptr, DD, FFF, 1, 1);

        if (l == 0) convert4_kernel<<<2048, 256>>>((const float4*)head_w, wh, (size_t)VV*DD/4);
    }

    rmsnorm_split<<<MR, 256>>>(h_, norm_w, nh, nl);

    // LM head: single-pass A
    gemm_mma<<<dim3(MR / 128, VV / 128), 256, GSMEM>>>(
        nh, nl, wh, nullptr,
        nullptr, out, nullptr, nullptr, VV, DD, 0, 1);
}